// round 11
// baseline (speedup 1.0000x reference)
#include <cuda_runtime.h>
#include <math.h>

// Problem: x [16,3,1024,1024] f32, to_gray [3] f32 -> out [16,1024,1024] f32
// gray -> 5x5 gaussian blur (SAME, zero pad) -> jnp.gradient-style Hessian ->
// 2x2 symmetric eig -> per-batch gamma = max(s)/2 -> Frangi-like response.

#define HH 1024
#define WW 1024
#define BB 16

static const size_t NPIX = (size_t)HH * WW;

// Scratch (static device allocations; no cudaMalloc anywhere)
__device__ float g_blur[(size_t)BB * HH * WW];   // 64 MiB blurred gray
__device__ float g_pmax[BB * 1024];              // per-block partial maxima of s
__device__ float g_gamma[BB];                    // per-batch gamma

// ---------------------------------------------------------------------------
// Kernel 1: fused grayscale + separable 5x5 gaussian blur (zero padding).
// Tile 32x32 output, 36x36 gray halo in smem, horizontal pass into smem,
// vertical pass to global.
// ---------------------------------------------------------------------------
__global__ __launch_bounds__(256) void k_gray_blur(
    const float* __restrict__ x, const float* __restrict__ tg,
    float w0, float w1, float w2)
{
    __shared__ float sg[36][37];   // gray with +-2 halo (pad col to avoid conflicts)
    __shared__ float sh[36][32];   // horizontally blurred

    const int b  = blockIdx.z;
    const int bx = blockIdx.x * 32;
    const int by = blockIdx.y * 32;
    const int tid = threadIdx.y * 32 + threadIdx.x;

    const float c0 = __ldg(tg + 0);
    const float c1 = __ldg(tg + 1);
    const float c2 = __ldg(tg + 2);
    const float* xb = x + (size_t)b * 3 * NPIX;

    // Load gray halo tile (zero outside image — SAME conv pads with zeros)
    for (int idx = tid; idx < 36 * 36; idx += 256) {
        int r = idx / 36, c = idx - r * 36;
        int hh = by + r - 2, ww = bx + c - 2;
        float v = 0.0f;
        if (hh >= 0 && hh < HH && ww >= 0 && ww < WW) {
            size_t o = (size_t)hh * WW + ww;
            v = c0 * __ldg(xb + o) + c1 * __ldg(xb + NPIX + o) + c2 * __ldg(xb + 2 * NPIX + o);
        }
        sg[r][c] = v;
    }
    __syncthreads();

    // Horizontal blur: 36 rows x 32 output cols
    for (int idx = tid; idx < 36 * 32; idx += 256) {
        int r = idx >> 5, c = idx & 31;
        float acc = w2 * sg[r][c];
        acc += w1 * sg[r][c + 1];
        acc += w0 * sg[r][c + 2];
        acc += w1 * sg[r][c + 3];
        acc += w2 * sg[r][c + 4];
        sh[r][c] = acc;
    }
    __syncthreads();

    // Vertical blur, write g
    float* gb = g_blur + (size_t)b * NPIX;
    for (int rr = threadIdx.y; rr < 32; rr += 8) {
        float acc = w2 * sh[rr][threadIdx.x];
        acc += w1 * sh[rr + 1][threadIdx.x];
        acc += w0 * sh[rr + 2][threadIdx.x];
        acc += w1 * sh[rr + 3][threadIdx.x];
        acc += w2 * sh[rr + 4][threadIdx.x];
        gb[(size_t)(by + rr) * WW + bx + threadIdx.x] = acc;
    }
}

// ---------------------------------------------------------------------------
// Stencil helpers over an smem tile of g with +-2 halo.
// jnp.gradient semantics: central differences interior, one-sided at edges.
// Formula selection is by GLOBAL index; clamped halo values are never consumed
// by the edge formulas.
// ---------------------------------------------------------------------------
__device__ __forceinline__ void load_tile(const float* __restrict__ gb,
                                          int bx, int by,
                                          float (*sg)[37], int tid)
{
    for (int idx = tid; idx < 36 * 36; idx += 256) {
        int r = idx / 36, c = idx - r * 36;
        int hh = min(HH - 1, max(0, by + r - 2));
        int ww = min(WW - 1, max(0, bx + c - 2));
        sg[r][c] = __ldg(gb + (size_t)hh * WW + ww);
    }
}

__device__ __forceinline__ float sgx(const float (*sg)[37], int li, int lj, int gi)
{
    if (gi == 0)      return sg[li + 1][lj] - sg[li][lj];
    if (gi == HH - 1) return sg[li][lj] - sg[li - 1][lj];
    return 0.5f * (sg[li + 1][lj] - sg[li - 1][lj]);
}

__device__ __forceinline__ float sgy(const float (*sg)[37], int li, int lj, int gj)
{
    if (gj == 0)      return sg[li][lj + 1] - sg[li][lj];
    if (gj == WW - 1) return sg[li][lj] - sg[li][lj - 1];
    return 0.5f * (sg[li][lj + 1] - sg[li][lj - 1]);
}

__device__ __forceinline__ void hess(const float (*sg)[37], int li, int lj,
                                     int gi, int gj,
                                     float& h00, float& h01, float& h11)
{
    // h00 = d/di of gx
    if (gi == 0)           h00 = sgx(sg, li + 1, lj, 1) - sgx(sg, li, lj, 0);
    else if (gi == HH - 1) h00 = sgx(sg, li, lj, HH - 1) - sgx(sg, li - 1, lj, HH - 2);
    else                   h00 = 0.5f * (sgx(sg, li + 1, lj, gi + 1) - sgx(sg, li - 1, lj, gi - 1));
    // h01 = d/dj of gx
    if (gj == 0)           h01 = sgx(sg, li, lj + 1, gi) - sgx(sg, li, lj, gi);
    else if (gj == WW - 1) h01 = sgx(sg, li, lj, gi) - sgx(sg, li, lj - 1, gi);
    else                   h01 = 0.5f * (sgx(sg, li, lj + 1, gi) - sgx(sg, li, lj - 1, gi));
    // h11 = d/dj of gy
    if (gj == 0)           h11 = sgy(sg, li, lj + 1, 1) - sgy(sg, li, lj, 0);
    else if (gj == WW - 1) h11 = sgy(sg, li, lj, WW - 1) - sgy(sg, li, lj - 1, WW - 2);
    else                   h11 = 0.5f * (sgy(sg, li, lj + 1, gj + 1) - sgy(sg, li, lj - 1, gj - 1));
}

__device__ __forceinline__ void eig2(float h00, float h01, float h11,
                                     float& e0, float& e1)
{
    float mean = 0.5f * (h00 + h11);
    float d    = 0.5f * (h00 - h11);
    float disc = sqrtf(d * d + h01 * h01);
    e0 = mean - disc;
    e1 = mean + disc;
}

// ---------------------------------------------------------------------------
// Kernel 2: per-block max of s = sqrt(e0^2+e1^2), written to g_pmax.
// ---------------------------------------------------------------------------
__global__ __launch_bounds__(256) void k_smax()
{
    __shared__ float sg[36][37];
    __shared__ float red[8];

    const int b  = blockIdx.z;
    const int bx = blockIdx.x * 32;
    const int by = blockIdx.y * 32;
    const int tid = threadIdx.y * 32 + threadIdx.x;
    const float* gb = g_blur + (size_t)b * NPIX;

    load_tile(gb, bx, by, sg, tid);
    __syncthreads();

    float m = 0.0f;
    const int lj = threadIdx.x + 2;
    const int gj = bx + threadIdx.x;
    for (int rr = threadIdx.y; rr < 32; rr += 8) {
        int li = rr + 2, gi = by + rr;
        float h00, h01, h11;
        hess(sg, li, lj, gi, gj, h00, h01, h11);
        float e0, e1;
        eig2(h00, h01, h11, e0, e1);
        float s = sqrtf(e0 * e0 + e1 * e1);
        m = fmaxf(m, s);
    }
    #pragma unroll
    for (int o = 16; o; o >>= 1)
        m = fmaxf(m, __shfl_xor_sync(0xffffffffu, m, o));
    if (threadIdx.x == 0) red[threadIdx.y] = m;
    __syncthreads();
    if (tid == 0) {
        float mm = red[0];
        #pragma unroll
        for (int i = 1; i < 8; i++) mm = fmaxf(mm, red[i]);
        g_pmax[b * 1024 + blockIdx.y * 32 + blockIdx.x] = mm;
    }
}

// ---------------------------------------------------------------------------
// Kernel 3: reduce partials -> gamma[b] = max_s/2; if ALL gammas are 0 set all
// to 1 (matches jnp.where(jnp.all(gamma==0), 1.0, gamma)).
// ---------------------------------------------------------------------------
__global__ void k_gamma()
{
    __shared__ float red[256];
    const int t = threadIdx.x;
    for (int b = 0; b < BB; b++) {
        const float* p = g_pmax + b * 1024;
        float m = fmaxf(fmaxf(p[t], p[t + 256]), fmaxf(p[t + 512], p[t + 768]));
        red[t] = m;
        __syncthreads();
        for (int off = 128; off; off >>= 1) {
            if (t < off) red[t] = fmaxf(red[t], red[t + off]);
            __syncthreads();
        }
        if (t == 0) g_gamma[b] = red[0] * 0.5f;
        __syncthreads();
    }
    if (t == 0) {
        bool allz = true;
        for (int b = 0; b < BB; b++)
            if (g_gamma[b] != 0.0f) allz = false;
        if (allz)
            for (int b = 0; b < BB; b++) g_gamma[b] = 1.0f;
    }
}

// ---------------------------------------------------------------------------
// Kernel 4: recompute Hessian stencil, eigenvalues, and final response.
// ---------------------------------------------------------------------------
__global__ __launch_bounds__(256) void k_out(float* __restrict__ out)
{
    __shared__ float sg[36][37];

    const int b  = blockIdx.z;
    const int bx = blockIdx.x * 32;
    const int by = blockIdx.y * 32;
    const int tid = threadIdx.y * 32 + threadIdx.x;
    const float* gb = g_blur + (size_t)b * NPIX;

    load_tile(gb, bx, by, sg, tid);
    __syncthreads();

    const float gamma = g_gamma[b];
    const float denom = (gamma * gamma) * 2.0f;   // 2 * gamma^2
    float* ob = out + (size_t)b * NPIX;

    const int lj = threadIdx.x + 2;
    const int gj = bx + threadIdx.x;
    for (int rr = threadIdx.y; rr < 32; rr += 8) {
        int li = rr + 2, gi = by + rr;
        float h00, h01, h11;
        hess(sg, li, lj, gi, gj, h00, h01, h11);
        float e0, e1;
        eig2(h00, h01, h11, e0, e1);

        bool sw    = fabsf(e1) < fabsf(e0);
        float lam1 = sw ? e1 : e0;
        float lam2 = fmaxf(sw ? e0 : e1, 1e-10f);
        float rb   = fabsf(lam1) / lam2;
        float s    = sqrtf(e0 * e0 + e1 * e1);

        // BETA=0.5 -> 2*BETA^2 = 0.5 -> divide is exact *2
        float vals = expf(-(rb * rb) * 2.0f) * (1.0f - expf(-(s * s) / denom));
        float f = fmaxf(0.0f, vals);
        ob[(size_t)gi * WW + gj] = (f <= 0.0f) ? 1.0f : f;
    }
}

// ---------------------------------------------------------------------------
extern "C" void kernel_launch(void* const* d_in, const int* in_sizes, int n_in,
                              void* d_out, int out_size)
{
    const float* x  = (const float*)d_in[0];
    const float* tg = (const float*)d_in[1];
    if (n_in >= 2 && in_sizes[0] == 3) {  // robust to input ordering
        const float* t = x; x = tg; tg = t;
    }

    // Separable normalized Gaussian weights, L=5, sig=10:
    // w_i = exp(-0.5*i^2/100) / (1 + 2e^{-0.005} + 2e^{-0.02})
    double e1d = exp(-0.005), e2d = exp(-0.02);
    double S = 1.0 + 2.0 * e1d + 2.0 * e2d;
    float w0 = (float)(1.0 / S);
    float w1 = (float)(e1d / S);
    float w2 = (float)(e2d / S);

    dim3 blk(32, 8);
    dim3 grd(WW / 32, HH / 32, BB);

    k_gray_blur<<<grd, blk>>>(x, tg, w0, w1, w2);
    k_smax<<<grd, blk>>>();
    k_gamma<<<1, 256>>>();
    k_out<<<grd, blk>>>((float*)d_out);
}

// round 12
// speedup vs baseline: 1.5039x; 1.5039x over previous
#include <cuda_runtime.h>
#include <math.h>

// Hessian_49160195670508: x [16,3,1024,1024] f32, to_gray [3] -> out [16,1024,1024]
// gray -> 5x5 gaussian blur (SAME, zero pad) -> jnp.gradient Hessian ->
// 2x2 symmetric eig -> per-batch gamma = max(s)/2 -> Frangi-like response.

#define HH 1024
#define WW 1024
#define BB 16
#define NPIX ((size_t)HH * WW)

// Static device scratch (no cudaMalloc anywhere)
__device__ float g_blur[(size_t)BB * HH * WW];   // 64 MiB blurred gray
__device__ float g_pmax[BB * 1024];              // per-block partial max of s^2
__device__ float g_gamma[BB];                    // per-batch gamma

// ---------------------------------------------------------------------------
// Kernel 1: fused grayscale + separable 5x5 gaussian blur (zero padding).
// Gray halo tile 36 rows x 40 cols (base bx-4, 16B aligned -> float4 loads).
// ---------------------------------------------------------------------------
__global__ __launch_bounds__(256) void k_gray_blur(
    const float* __restrict__ x, const float* __restrict__ tg,
    float w0, float w1, float w2)
{
    __shared__ float sg[36][44];   // gray, global cols bx-4 .. bx+35
    __shared__ float sh[36][33];   // horizontally blurred, cols bx .. bx+31

    const int b  = blockIdx.z;
    const int bx = blockIdx.x * 32;
    const int by = blockIdx.y * 32;
    const int tx = threadIdx.x, ty = threadIdx.y;
    const int tid = ty * 32 + tx;

    const float c0 = __ldg(tg + 0);
    const float c1 = __ldg(tg + 1);
    const float c2 = __ldg(tg + 2);
    const float* xb = x + (size_t)b * 3 * NPIX;

    const bool xedge = (blockIdx.x == 0) || (blockIdx.x == (WW / 32 - 1));

    if (!xedge) {
        // float4 path: 36 rows x 10 float4 (cols bx-4..bx+35, all in-image)
        for (int idx = tid; idx < 360; idx += 256) {
            int r  = idx / 10;
            int c4 = (idx - r * 10) * 4;
            int hh = by + r - 2;
            float4 g4 = make_float4(0.f, 0.f, 0.f, 0.f);
            if (hh >= 0 && hh < HH) {
                size_t o = (size_t)hh * WW + (bx - 4) + c4;
                float4 a = *(const float4*)(xb + o);
                float4 v = *(const float4*)(xb + NPIX + o);
                float4 w = *(const float4*)(xb + 2 * NPIX + o);
                g4.x = c0 * a.x + c1 * v.x + c2 * w.x;
                g4.y = c0 * a.y + c1 * v.y + c2 * w.y;
                g4.z = c0 * a.z + c1 * v.z + c2 * w.z;
                g4.w = c0 * a.w + c1 * v.w + c2 * w.w;
            }
            *(float4*)&sg[r][c4] = g4;
        }
    } else {
        // scalar path with zero padding on both axes
        for (int idx = tid; idx < 1440; idx += 256) {
            int r  = idx / 40;
            int c  = idx - r * 40;
            int hh = by + r - 2;
            int wc = bx - 4 + c;
            float v = 0.f;
            if (hh >= 0 && hh < HH && wc >= 0 && wc < WW) {
                size_t o = (size_t)hh * WW + wc;
                v = c0 * __ldg(xb + o) + c1 * __ldg(xb + NPIX + o)
                  + c2 * __ldg(xb + 2 * NPIX + o);
            }
            sg[r][c] = v;
        }
    }
    __syncthreads();

    // Horizontal blur: 36 rows x 32 output cols
    for (int idx = tid; idx < 1152; idx += 256) {
        int r = idx >> 5, c = idx & 31, lc = c + 4;
        sh[r][c] = w0 * sg[r][lc]
                 + w1 * (sg[r][lc - 1] + sg[r][lc + 1])
                 + w2 * (sg[r][lc - 2] + sg[r][lc + 2]);
    }
    __syncthreads();

    // Vertical blur: each thread 4 consecutive rows, register-cached column
    const int r0 = ty * 4;
    float vv[8];
    #pragma unroll
    for (int t = 0; t < 8; t++) vv[t] = sh[r0 + t][tx];

    float* gb = g_blur + (size_t)b * NPIX;
    #pragma unroll
    for (int k = 0; k < 4; k++) {
        float g = w0 * vv[k + 2]
                + w1 * (vv[k + 1] + vv[k + 3])
                + w2 * (vv[k] + vv[k + 4]);
        gb[(size_t)(by + r0 + k) * WW + bx + tx] = g;
    }
}

// ---------------------------------------------------------------------------
// Halo tile loader for the stencil kernels (clamped indexing).
// ---------------------------------------------------------------------------
__device__ __forceinline__ void load_tile4(const float* __restrict__ gb,
                                           int bx, int by,
                                           float (*sg)[44], int tid, bool xedge)
{
    if (!xedge) {
        for (int idx = tid; idx < 360; idx += 256) {
            int r  = idx / 10;
            int c4 = (idx - r * 10) * 4;
            int hh = min(HH - 1, max(0, by + r - 2));
            *(float4*)&sg[r][c4] =
                *(const float4*)(gb + (size_t)hh * WW + (bx - 4) + c4);
        }
    } else {
        for (int idx = tid; idx < 1440; idx += 256) {
            int r  = idx / 40;
            int c  = idx - r * 40;
            int hh = min(HH - 1, max(0, by + r - 2));
            int wc = min(WW - 1, max(0, bx - 4 + c));
            sg[r][c] = __ldg(gb + (size_t)hh * WW + wc);
        }
    }
}

// ---------------------------------------------------------------------------
// Generic (edge-correct) jnp.gradient stencil — same as the verified R11 code.
// ---------------------------------------------------------------------------
__device__ __forceinline__ float sgx(const float (*sg)[44], int li, int lj, int gi)
{
    if (gi == 0)      return sg[li + 1][lj] - sg[li][lj];
    if (gi == HH - 1) return sg[li][lj] - sg[li - 1][lj];
    return 0.5f * (sg[li + 1][lj] - sg[li - 1][lj]);
}

__device__ __forceinline__ float sgy(const float (*sg)[44], int li, int lj, int gj)
{
    if (gj == 0)      return sg[li][lj + 1] - sg[li][lj];
    if (gj == WW - 1) return sg[li][lj] - sg[li][lj - 1];
    return 0.5f * (sg[li][lj + 1] - sg[li][lj - 1]);
}

__device__ __forceinline__ void hess_generic(const float (*sg)[44], int li, int lj,
                                             int gi, int gj,
                                             float& h00, float& h01, float& h11)
{
    if (gi == 0)           h00 = sgx(sg, li + 1, lj, 1) - sgx(sg, li, lj, 0);
    else if (gi == HH - 1) h00 = sgx(sg, li, lj, HH - 1) - sgx(sg, li - 1, lj, HH - 2);
    else                   h00 = 0.5f * (sgx(sg, li + 1, lj, gi + 1) - sgx(sg, li - 1, lj, gi - 1));

    if (gj == 0)           h01 = sgx(sg, li, lj + 1, gi) - sgx(sg, li, lj, gi);
    else if (gj == WW - 1) h01 = sgx(sg, li, lj, gi) - sgx(sg, li, lj - 1, gi);
    else                   h01 = 0.5f * (sgx(sg, li, lj + 1, gi) - sgx(sg, li, lj - 1, gi));

    if (gj == 0)           h11 = sgy(sg, li, lj + 1, 1) - sgy(sg, li, lj, 0);
    else if (gj == WW - 1) h11 = sgy(sg, li, lj, WW - 1) - sgy(sg, li, lj - 1, WW - 2);
    else                   h11 = 0.5f * (sgy(sg, li, lj + 1, gj + 1) - sgy(sg, li, lj - 1, gj - 1));
}

// ---------------------------------------------------------------------------
// Fast interior stencil: pure central differences, register-cached columns,
// 4 consecutive rows per thread, 28 LDS -> 12 Hessian values.
// ---------------------------------------------------------------------------
__device__ __forceinline__ void hess4_fast(const float (*sg)[44], int r0, int lj,
                                           float* h00, float* h01, float* h11)
{
    float v[8], a[6], bc[6], cl[4], cr[4];
    #pragma unroll
    for (int t = 0; t < 8; t++) v[t] = sg[r0 + t][lj];
    #pragma unroll
    for (int t = 0; t < 6; t++) { a[t]  = sg[r0 + 1 + t][lj - 1];
                                  bc[t] = sg[r0 + 1 + t][lj + 1]; }
    #pragma unroll
    for (int t = 0; t < 4; t++) { cl[t] = sg[r0 + 2 + t][lj - 2];
                                  cr[t] = sg[r0 + 2 + t][lj + 2]; }
    #pragma unroll
    for (int k = 0; k < 4; k++) {
        h00[k] = 0.25f * (v[k] + v[k + 4]) - 0.5f * v[k + 2];
        h01[k] = 0.25f * ((bc[k + 2] - a[k + 2]) - (bc[k] - a[k]));
        h11[k] = 0.25f * (cl[k] + cr[k]) - 0.5f * v[k + 2];
    }
}

// ---------------------------------------------------------------------------
// Kernel 2: per-block max of s^2 (no sqrt: s^2 = 2*(mean^2 + q)).
// ---------------------------------------------------------------------------
__global__ __launch_bounds__(256) void k_smax()
{
    __shared__ float sg[36][44];
    __shared__ float red[8];

    const int b  = blockIdx.z;
    const int bx = blockIdx.x * 32;
    const int by = blockIdx.y * 32;
    const int tx = threadIdx.x, ty = threadIdx.y;
    const int tid = ty * 32 + tx;
    const float* gb = g_blur + (size_t)b * NPIX;

    const bool xedge = (blockIdx.x == 0) || (blockIdx.x == (WW / 32 - 1));
    const bool edge  = xedge || (blockIdx.y == 0) || (blockIdx.y == (HH / 32 - 1));

    load_tile4(gb, bx, by, sg, tid, xedge);
    __syncthreads();

    const int lj = tx + 4;
    const int r0 = ty * 4;
    float m = 0.0f;

    if (!edge) {
        float h00[4], h01[4], h11[4];
        hess4_fast(sg, r0, lj, h00, h01, h11);
        #pragma unroll
        for (int k = 0; k < 4; k++) {
            float mean = 0.5f * (h00[k] + h11[k]);
            float d    = 0.5f * (h00[k] - h11[k]);
            float q    = fmaf(d, d, h01[k] * h01[k]);
            float s2   = 2.0f * fmaf(mean, mean, q);
            m = fmaxf(m, s2);
        }
    } else {
        const int gj = bx + tx;
        #pragma unroll
        for (int k = 0; k < 4; k++) {
            int li = r0 + 2 + k, gi = by + r0 + k;
            float h00, h01, h11;
            hess_generic(sg, li, lj, gi, gj, h00, h01, h11);
            float mean = 0.5f * (h00 + h11);
            float d    = 0.5f * (h00 - h11);
            float q    = fmaf(d, d, h01 * h01);
            float s2   = 2.0f * fmaf(mean, mean, q);
            m = fmaxf(m, s2);
        }
    }

    #pragma unroll
    for (int o = 16; o; o >>= 1)
        m = fmaxf(m, __shfl_xor_sync(0xffffffffu, m, o));
    if (tx == 0) red[ty] = m;
    __syncthreads();
    if (tid == 0) {
        float mm = red[0];
        #pragma unroll
        for (int i = 1; i < 8; i++) mm = fmaxf(mm, red[i]);
        g_pmax[b * 1024 + blockIdx.y * 32 + blockIdx.x] = mm;
    }
}

// ---------------------------------------------------------------------------
// Kernel 3: gamma[b] = sqrt(max s^2)/2; if ALL gammas are 0, set all to 1.
// ---------------------------------------------------------------------------
__global__ void k_gamma()
{
    __shared__ float red[256];
    const int t = threadIdx.x;
    for (int b = 0; b < BB; b++) {
        const float* p = g_pmax + b * 1024;
        float m = fmaxf(fmaxf(p[t], p[t + 256]), fmaxf(p[t + 512], p[t + 768]));
        red[t] = m;
        __syncthreads();
        for (int off = 128; off; off >>= 1) {
            if (t < off) red[t] = fmaxf(red[t], red[t + off]);
            __syncthreads();
        }
        if (t == 0) g_gamma[b] = 0.5f * sqrtf(red[0]);
        __syncthreads();
    }
    if (t == 0) {
        bool allz = true;
        for (int b = 0; b < BB; b++)
            if (g_gamma[b] != 0.0f) allz = false;
        if (allz)
            for (int b = 0; b < BB; b++) g_gamma[b] = 1.0f;
    }
}

// ---------------------------------------------------------------------------
// Response: eigenvalues + Frangi factors. s only enters squared -> no sqrt(s).
// ---------------------------------------------------------------------------
__device__ __forceinline__ float response(float h00, float h01, float h11,
                                          float denom)
{
    float mean = 0.5f * (h00 + h11);
    float d    = 0.5f * (h00 - h11);
    float q    = fmaf(d, d, h01 * h01);
    float disc = sqrtf(q);
    float e0   = mean - disc;
    float e1   = mean + disc;

    float ae0 = fabsf(e0), ae1 = fabsf(e1);
    float num  = fminf(ae0, ae1);                      // |lam1|
    float lam2 = fmaxf((ae1 < ae0) ? e0 : e1, 1e-10f); // larger-|.| eig, clamped
    float rb   = __fdividef(num, lam2);

    float s2   = fmaf(e0, e0, e1 * e1);
    float vals = expf(-2.0f * rb * rb)
               * (1.0f - expf(-__fdividef(s2, denom)));
    return (vals <= 0.0f) ? 1.0f : vals;
}

// ---------------------------------------------------------------------------
// Kernel 4: final output.
// ---------------------------------------------------------------------------
__global__ __launch_bounds__(256) void k_out(float* __restrict__ out)
{
    __shared__ float sg[36][44];

    const int b  = blockIdx.z;
    const int bx = blockIdx.x * 32;
    const int by = blockIdx.y * 32;
    const int tx = threadIdx.x, ty = threadIdx.y;
    const int tid = ty * 32 + tx;
    const float* gb = g_blur + (size_t)b * NPIX;

    const bool xedge = (blockIdx.x == 0) || (blockIdx.x == (WW / 32 - 1));
    const bool edge  = xedge || (blockIdx.y == 0) || (blockIdx.y == (HH / 32 - 1));

    load_tile4(gb, bx, by, sg, tid, xedge);
    __syncthreads();

    const float gamma = g_gamma[b];
    const float denom = 2.0f * gamma * gamma;
    float* ob = out + (size_t)b * NPIX;

    const int lj = tx + 4;
    const int r0 = ty * 4;

    if (!edge) {
        float h00[4], h01[4], h11[4];
        hess4_fast(sg, r0, lj, h00, h01, h11);
        #pragma unroll
        for (int k = 0; k < 4; k++) {
            ob[(size_t)(by + r0 + k) * WW + bx + tx] =
                response(h00[k], h01[k], h11[k], denom);
        }
    } else {
        const int gj = bx + tx;
        #pragma unroll
        for (int k = 0; k < 4; k++) {
            int li = r0 + 2 + k, gi = by + r0 + k;
            float h00, h01, h11;
            hess_generic(sg, li, lj, gi, gj, h00, h01, h11);
            ob[(size_t)gi * WW + gj] = response(h00, h01, h11, denom);
        }
    }
}

// ---------------------------------------------------------------------------
extern "C" void kernel_launch(void* const* d_in, const int* in_sizes, int n_in,
                              void* d_out, int out_size)
{
    const float* x  = (const float*)d_in[0];
    const float* tg = (const float*)d_in[1];
    if (n_in >= 2 && in_sizes[0] == 3) {  // robust to input ordering
        const float* t = x; x = tg; tg = t;
    }

    // Separable normalized Gaussian weights, L=5, sig=10.
    double e1d = exp(-0.005), e2d = exp(-0.02);
    double S = 1.0 + 2.0 * e1d + 2.0 * e2d;
    float w0 = (float)(1.0 / S);
    float w1 = (float)(e1d / S);
    float w2 = (float)(e2d / S);

    dim3 blk(32, 8);
    dim3 grd(WW / 32, HH / 32, BB);

    k_gray_blur<<<grd, blk>>>(x, tg, w0, w1, w2);
    k_smax<<<grd, blk>>>();
    k_gamma<<<1, 256>>>();
    k_out<<<grd, blk>>>((float*)d_out);
}

// round 13
// speedup vs baseline: 1.6026x; 1.0656x over previous
#include <cuda_runtime.h>
#include <math.h>

// Hessian_49160195670508: x [16,3,1024,1024] f32, to_gray [3] -> out [16,1024,1024]
// gray -> 5x5 gaussian blur (SAME, zero pad) -> jnp.gradient Hessian ->
// 2x2 symmetric eig -> per-batch gamma = max(s)/2 -> Frangi-like response.

#define HH 1024
#define WW 1024
#define BB 16
#define NPIX ((size_t)HH * WW)

// Static device scratch (no cudaMalloc anywhere)
__device__ float g_blur[(size_t)BB * HH * WW];   // 64 MiB blurred gray
__device__ float g_pmax[BB * 1024];              // per-block partial max of s^2
__device__ float g_gamma[BB];                    // per-batch gamma

// ---------------------------------------------------------------------------
// Generic (edge-correct) jnp.gradient stencil over a blurred tile sg[36][44]
// whose element [r][c] is blur(by-2+r, bx-4+c). Only c in 2..37 is valid;
// formula selection by GLOBAL index guarantees invalid cells are never read.
// ---------------------------------------------------------------------------
__device__ __forceinline__ float sgx(const float (*sg)[44], int li, int lj, int gi)
{
    if (gi == 0)      return sg[li + 1][lj] - sg[li][lj];
    if (gi == HH - 1) return sg[li][lj] - sg[li - 1][lj];
    return 0.5f * (sg[li + 1][lj] - sg[li - 1][lj]);
}

__device__ __forceinline__ float sgy(const float (*sg)[44], int li, int lj, int gj)
{
    if (gj == 0)      return sg[li][lj + 1] - sg[li][lj];
    if (gj == WW - 1) return sg[li][lj] - sg[li][lj - 1];
    return 0.5f * (sg[li][lj + 1] - sg[li][lj - 1]);
}

__device__ __forceinline__ void hess_generic(const float (*sg)[44], int li, int lj,
                                             int gi, int gj,
                                             float& h00, float& h01, float& h11)
{
    if (gi == 0)           h00 = sgx(sg, li + 1, lj, 1) - sgx(sg, li, lj, 0);
    else if (gi == HH - 1) h00 = sgx(sg, li, lj, HH - 1) - sgx(sg, li - 1, lj, HH - 2);
    else                   h00 = 0.5f * (sgx(sg, li + 1, lj, gi + 1) - sgx(sg, li - 1, lj, gi - 1));

    if (gj == 0)           h01 = sgx(sg, li, lj + 1, gi) - sgx(sg, li, lj, gi);
    else if (gj == WW - 1) h01 = sgx(sg, li, lj, gi) - sgx(sg, li, lj - 1, gi);
    else                   h01 = 0.5f * (sgx(sg, li, lj + 1, gi) - sgx(sg, li, lj - 1, gi));

    if (gj == 0)           h11 = sgy(sg, li, lj + 1, 1) - sgy(sg, li, lj, 0);
    else if (gj == WW - 1) h11 = sgy(sg, li, lj, WW - 1) - sgy(sg, li, lj - 1, WW - 2);
    else                   h11 = 0.5f * (sgy(sg, li, lj + 1, gj + 1) - sgy(sg, li, lj - 1, gj - 1));
}

// Fast interior stencil: pure central 2nd differences, 4 consecutive rows
// per thread with register-cached columns.
__device__ __forceinline__ void hess4_fast(const float (*sg)[44], int r0, int lj,
                                           float* h00, float* h01, float* h11)
{
    float v[8], a[6], bc[6], cl[4], cr[4];
    #pragma unroll
    for (int t = 0; t < 8; t++) v[t] = sg[r0 + t][lj];
    #pragma unroll
    for (int t = 0; t < 6; t++) { a[t]  = sg[r0 + 1 + t][lj - 1];
                                  bc[t] = sg[r0 + 1 + t][lj + 1]; }
    #pragma unroll
    for (int t = 0; t < 4; t++) { cl[t] = sg[r0 + 2 + t][lj - 2];
                                  cr[t] = sg[r0 + 2 + t][lj + 2]; }
    #pragma unroll
    for (int k = 0; k < 4; k++) {
        h00[k] = 0.25f * (v[k] + v[k + 4]) - 0.5f * v[k + 2];
        h01[k] = 0.25f * ((bc[k + 2] - a[k + 2]) - (bc[k] - a[k]));
        h11[k] = 0.25f * (cl[k] + cr[k]) - 0.5f * v[k + 2];
    }
}

// ---------------------------------------------------------------------------
// Kernel 1 (FUSED): grayscale + separable 5x5 blur + write g_blur + per-block
// max of s^2 -- the blurred tile never leaves shared memory for the stencil.
// Gray halo: rows by-4..by+35, cols bx-4..bx+35 (zero pad outside image).
// Blurred tile sb[36][44]: [r][c] = blur(by-2+r, bx-4+c), valid c in 2..37.
// ---------------------------------------------------------------------------
__global__ __launch_bounds__(256) void k_blur_smax(
    const float* __restrict__ x, const float* __restrict__ tg,
    float w0, float w1, float w2)
{
    __shared__ float sgr[40][44];  // gray, rows by-4.., cols bx-4..bx+35
    __shared__ float sh[40][37];   // horiz blurred, cols bx-2..bx+33
    __shared__ float sb[36][44];   // fully blurred, rows by-2.., cols base bx-4
    __shared__ float red[8];

    const int b  = blockIdx.z;
    const int bx = blockIdx.x * 32;
    const int by = blockIdx.y * 32;
    const int tx = threadIdx.x, ty = threadIdx.y;
    const int tid = ty * 32 + tx;

    const float c0 = __ldg(tg + 0);
    const float c1 = __ldg(tg + 1);
    const float c2 = __ldg(tg + 2);
    const float* xb = x + (size_t)b * 3 * NPIX;

    const bool xedge = (blockIdx.x == 0) || (blockIdx.x == (WW / 32 - 1));
    const bool edge  = xedge || (blockIdx.y == 0) || (blockIdx.y == (HH / 32 - 1));

    // ---- load gray halo (zero outside image: SAME conv zero-pads) ----
    if (!xedge) {
        for (int idx = tid; idx < 400; idx += 256) {
            int r  = idx / 10;
            int c4 = (idx - r * 10) * 4;
            int hh = by + r - 4;
            float4 g4 = make_float4(0.f, 0.f, 0.f, 0.f);
            if (hh >= 0 && hh < HH) {
                size_t o = (size_t)hh * WW + (bx - 4) + c4;
                float4 a = *(const float4*)(xb + o);
                float4 v = *(const float4*)(xb + NPIX + o);
                float4 w = *(const float4*)(xb + 2 * NPIX + o);
                g4.x = c0 * a.x + c1 * v.x + c2 * w.x;
                g4.y = c0 * a.y + c1 * v.y + c2 * w.y;
                g4.z = c0 * a.z + c1 * v.z + c2 * w.z;
                g4.w = c0 * a.w + c1 * v.w + c2 * w.w;
            }
            *(float4*)&sgr[r][c4] = g4;
        }
    } else {
        for (int idx = tid; idx < 1600; idx += 256) {
            int r  = idx / 40;
            int c  = idx - r * 40;
            int hh = by + r - 4;
            int wc = bx - 4 + c;
            float v = 0.f;
            if (hh >= 0 && hh < HH && wc >= 0 && wc < WW) {
                size_t o = (size_t)hh * WW + wc;
                v = c0 * __ldg(xb + o) + c1 * __ldg(xb + NPIX + o)
                  + c2 * __ldg(xb + 2 * NPIX + o);
            }
            sgr[r][c] = v;
        }
    }
    __syncthreads();

    // ---- horizontal blur: 40 rows x 36 cols (global cols bx-2..bx+33) ----
    for (int idx = tid; idx < 1440; idx += 256) {
        int r = idx / 36, c = idx - r * 36;   // sh col c -> gray col index c+2
        sh[r][c] = w0 * sgr[r][c + 2]
                 + w1 * (sgr[r][c + 1] + sgr[r][c + 3])
                 + w2 * (sgr[r][c] + sgr[r][c + 4]);
    }
    __syncthreads();

    // ---- vertical blur: 36 rows x 36 cols into sb (col offset +2) ----
    for (int idx = tid; idx < 1296; idx += 256) {
        int r = idx / 36, c = idx - r * 36;
        sb[r][c + 2] = w0 * sh[r + 2][c]
                     + w1 * (sh[r + 1][c] + sh[r + 3][c])
                     + w2 * (sh[r][c] + sh[r + 4][c]);
    }
    __syncthreads();

    // ---- write blurred center 32x32 to global ----
    float* gb = g_blur + (size_t)b * NPIX;
    const int r0 = ty * 4;
    #pragma unroll
    for (int k = 0; k < 4; k++)
        gb[(size_t)(by + r0 + k) * WW + bx + tx] = sb[r0 + 2 + k][tx + 4];

    // ---- per-block max of s^2 on the in-smem blurred tile ----
    const int lj = tx + 4;
    float m = 0.0f;
    if (!edge) {
        float h00[4], h01[4], h11[4];
        hess4_fast(sb, r0, lj, h00, h01, h11);
        #pragma unroll
        for (int k = 0; k < 4; k++) {
            float mean = 0.5f * (h00[k] + h11[k]);
            float d    = 0.5f * (h00[k] - h11[k]);
            float q    = fmaf(d, d, h01[k] * h01[k]);
            m = fmaxf(m, 2.0f * fmaf(mean, mean, q));
        }
    } else {
        const int gj = bx + tx;
        #pragma unroll
        for (int k = 0; k < 4; k++) {
            int li = r0 + 2 + k, gi = by + r0 + k;
            float h00, h01, h11;
            hess_generic(sb, li, lj, gi, gj, h00, h01, h11);
            float mean = 0.5f * (h00 + h11);
            float d    = 0.5f * (h00 - h11);
            float q    = fmaf(d, d, h01 * h01);
            m = fmaxf(m, 2.0f * fmaf(mean, mean, q));
        }
    }

    #pragma unroll
    for (int o = 16; o; o >>= 1)
        m = fmaxf(m, __shfl_xor_sync(0xffffffffu, m, o));
    if (tx == 0) red[ty] = m;
    __syncthreads();
    if (tid == 0) {
        float mm = red[0];
        #pragma unroll
        for (int i = 1; i < 8; i++) mm = fmaxf(mm, red[i]);
        g_pmax[b * 1024 + blockIdx.y * 32 + blockIdx.x] = mm;
    }
}

// ---------------------------------------------------------------------------
// Kernel 2: gamma[b] = sqrt(max s^2)/2, one warp per batch; all-zero check.
// ---------------------------------------------------------------------------
__global__ __launch_bounds__(512) void k_gamma()
{
    __shared__ float gm[BB];
    const int w    = threadIdx.x >> 5;   // warp = batch
    const int lane = threadIdx.x & 31;

    const float* p = g_pmax + w * 1024;
    float m = 0.0f;
    #pragma unroll
    for (int i = 0; i < 32; i++)
        m = fmaxf(m, p[lane + i * 32]);
    #pragma unroll
    for (int o = 16; o; o >>= 1)
        m = fmaxf(m, __shfl_xor_sync(0xffffffffu, m, o));
    if (lane == 0) gm[w] = 0.5f * sqrtf(m);
    __syncthreads();

    if (threadIdx.x == 0) {
        bool allz = true;
        #pragma unroll
        for (int b = 0; b < BB; b++)
            if (gm[b] != 0.0f) allz = false;
        #pragma unroll
        for (int b = 0; b < BB; b++)
            g_gamma[b] = allz ? 1.0f : gm[b];
    }
}

// ---------------------------------------------------------------------------
// Response. First exp factor via MUFU (__expf, arg in [-2,0], never
// flush-critical). Second factor keeps accurate expf: the 1-exp(..)->0->1.0
// flush boundary must match the reference.
// ---------------------------------------------------------------------------
__device__ __forceinline__ float response(float h00, float h01, float h11,
                                          float inv_denom)
{
    float mean = 0.5f * (h00 + h11);
    float d    = 0.5f * (h00 - h11);
    float q    = fmaf(d, d, h01 * h01);
    float disc = sqrtf(q);
    float e0   = mean - disc;
    float e1   = mean + disc;

    float ae0 = fabsf(e0), ae1 = fabsf(e1);
    float num  = fminf(ae0, ae1);                      // |lam1|
    float lam2 = fmaxf((ae1 < ae0) ? e0 : e1, 1e-10f); // larger-|.| eig, clamped
    float rb   = __fdividef(num, lam2);

    float s2   = fmaf(e0, e0, e1 * e1);
    float vals = __expf(-2.0f * rb * rb)
               * (1.0f - expf(-s2 * inv_denom));
    return (vals <= 0.0f) ? 1.0f : vals;
}

// ---------------------------------------------------------------------------
// Kernel 3: final output from g_blur.
// Tile sg[36][44]: [r][c] = blur(clamp(by-2+r), clamp(bx-4+c)).
// ---------------------------------------------------------------------------
__global__ __launch_bounds__(256) void k_out(float* __restrict__ out)
{
    __shared__ float sg[36][44];

    const int b  = blockIdx.z;
    const int bx = blockIdx.x * 32;
    const int by = blockIdx.y * 32;
    const int tx = threadIdx.x, ty = threadIdx.y;
    const int tid = ty * 32 + tx;
    const float* gb = g_blur + (size_t)b * NPIX;

    const bool xedge = (blockIdx.x == 0) || (blockIdx.x == (WW / 32 - 1));
    const bool edge  = xedge || (blockIdx.y == 0) || (blockIdx.y == (HH / 32 - 1));

    if (!xedge) {
        for (int idx = tid; idx < 360; idx += 256) {
            int r  = idx / 10;
            int c4 = (idx - r * 10) * 4;
            int hh = min(HH - 1, max(0, by + r - 2));
            *(float4*)&sg[r][c4] =
                *(const float4*)(gb + (size_t)hh * WW + (bx - 4) + c4);
        }
    } else {
        for (int idx = tid; idx < 1440; idx += 256) {
            int r  = idx / 40;
            int c  = idx - r * 40;
            int hh = min(HH - 1, max(0, by + r - 2));
            int wc = min(WW - 1, max(0, bx - 4 + c));
            sg[r][c] = __ldg(gb + (size_t)hh * WW + wc);
        }
    }
    __syncthreads();

    const float gamma = g_gamma[b];
    const float inv_denom = 1.0f / (2.0f * gamma * gamma);
    float* ob = out + (size_t)b * NPIX;

    const int lj = tx + 4;
    const int r0 = ty * 4;

    if (!edge) {
        float h00[4], h01[4], h11[4];
        hess4_fast(sg, r0, lj, h00, h01, h11);
        #pragma unroll
        for (int k = 0; k < 4; k++) {
            ob[(size_t)(by + r0 + k) * WW + bx + tx] =
                response(h00[k], h01[k], h11[k], inv_denom);
        }
    } else {
        const int gj = bx + tx;
        #pragma unroll
        for (int k = 0; k < 4; k++) {
            int li = r0 + 2 + k, gi = by + r0 + k;
            float h00, h01, h11;
            hess_generic(sg, li, lj, gi, gj, h00, h01, h11);
            ob[(size_t)gi * WW + gj] = response(h00, h01, h11, inv_denom);
        }
    }
}

// ---------------------------------------------------------------------------
extern "C" void kernel_launch(void* const* d_in, const int* in_sizes, int n_in,
                              void* d_out, int out_size)
{
    const float* x  = (const float*)d_in[0];
    const float* tg = (const float*)d_in[1];
    if (n_in >= 2 && in_sizes[0] == 3) {  // robust to input ordering
        const float* t = x; x = tg; tg = t;
    }

    // Separable normalized Gaussian weights, L=5, sig=10.
    double e1d = exp(-0.005), e2d = exp(-0.02);
    double S = 1.0 + 2.0 * e1d + 2.0 * e2d;
    float w0 = (float)(1.0 / S);
    float w1 = (float)(e1d / S);
    float w2 = (float)(e2d / S);

    dim3 blk(32, 8);
    dim3 grd(WW / 32, HH / 32, BB);

    k_blur_smax<<<grd, blk>>>(x, tg, w0, w1, w2);
    k_gamma<<<1, 512>>>();
    k_out<<<grd, blk>>>((float*)d_out);
}

// round 14
// speedup vs baseline: 1.6089x; 1.0039x over previous
#include <cuda_runtime.h>
#include <math.h>

// Hessian_49160195670508: x [16,3,1024,1024] f32, to_gray [3] -> out [16,1024,1024]
// gray -> 5x5 gaussian blur (SAME, zero pad) -> jnp.gradient Hessian ->
// 2x2 symmetric eig -> per-batch gamma = max(s)/2 -> Frangi-like response.

#define HH 1024
#define WW 1024
#define BB 16
#define NPIX ((size_t)HH * WW)

// Static device scratch (no cudaMalloc anywhere)
__device__ float g_blur[(size_t)BB * HH * WW];   // 64 MiB blurred gray
__device__ float g_pmax[BB * 1024];              // per-block partial max of s^2
__device__ float g_gamma[BB];                    // per-batch gamma

// ---------------------------------------------------------------------------
// Generic (edge-correct) jnp.gradient stencil over a blurred tile sg[36][44]
// whose element [r][c] is blur(by-2+r, bx-4+c). Only c in 2..37 is valid;
// formula selection by GLOBAL index guarantees invalid cells are never read.
// ---------------------------------------------------------------------------
__device__ __forceinline__ float sgx(const float (*sg)[44], int li, int lj, int gi)
{
    if (gi == 0)      return sg[li + 1][lj] - sg[li][lj];
    if (gi == HH - 1) return sg[li][lj] - sg[li - 1][lj];
    return 0.5f * (sg[li + 1][lj] - sg[li - 1][lj]);
}

__device__ __forceinline__ float sgy(const float (*sg)[44], int li, int lj, int gj)
{
    if (gj == 0)      return sg[li][lj + 1] - sg[li][lj];
    if (gj == WW - 1) return sg[li][lj] - sg[li][lj - 1];
    return 0.5f * (sg[li][lj + 1] - sg[li][lj - 1]);
}

__device__ __forceinline__ void hess_generic(const float (*sg)[44], int li, int lj,
                                             int gi, int gj,
                                             float& h00, float& h01, float& h11)
{
    if (gi == 0)           h00 = sgx(sg, li + 1, lj, 1) - sgx(sg, li, lj, 0);
    else if (gi == HH - 1) h00 = sgx(sg, li, lj, HH - 1) - sgx(sg, li - 1, lj, HH - 2);
    else                   h00 = 0.5f * (sgx(sg, li + 1, lj, gi + 1) - sgx(sg, li - 1, lj, gi - 1));

    if (gj == 0)           h01 = sgx(sg, li, lj + 1, gi) - sgx(sg, li, lj, gi);
    else if (gj == WW - 1) h01 = sgx(sg, li, lj, gi) - sgx(sg, li, lj - 1, gi);
    else                   h01 = 0.5f * (sgx(sg, li, lj + 1, gi) - sgx(sg, li, lj - 1, gi));

    if (gj == 0)           h11 = sgy(sg, li, lj + 1, 1) - sgy(sg, li, lj, 0);
    else if (gj == WW - 1) h11 = sgy(sg, li, lj, WW - 1) - sgy(sg, li, lj - 1, WW - 2);
    else                   h11 = 0.5f * (sgy(sg, li, lj + 1, gj + 1) - sgy(sg, li, lj - 1, gj - 1));
}

// Fast interior stencil: pure central 2nd differences, 4 consecutive rows
// per thread with register-cached columns.
__device__ __forceinline__ void hess4_fast(const float (*sg)[44], int r0, int lj,
                                           float* h00, float* h01, float* h11)
{
    float v[8], a[6], bc[6], cl[4], cr[4];
    #pragma unroll
    for (int t = 0; t < 8; t++) v[t] = sg[r0 + t][lj];
    #pragma unroll
    for (int t = 0; t < 6; t++) { a[t]  = sg[r0 + 1 + t][lj - 1];
                                  bc[t] = sg[r0 + 1 + t][lj + 1]; }
    #pragma unroll
    for (int t = 0; t < 4; t++) { cl[t] = sg[r0 + 2 + t][lj - 2];
                                  cr[t] = sg[r0 + 2 + t][lj + 2]; }
    #pragma unroll
    for (int k = 0; k < 4; k++) {
        h00[k] = 0.25f * (v[k] + v[k + 4]) - 0.5f * v[k + 2];
        h01[k] = 0.25f * ((bc[k + 2] - a[k + 2]) - (bc[k] - a[k]));
        h11[k] = 0.25f * (cl[k] + cr[k]) - 0.5f * v[k + 2];
    }
}

// ---------------------------------------------------------------------------
// Kernel 1 (FUSED): grayscale + separable 5x5 blur + write g_blur + per-block
// max of s^2 -- the blurred tile never leaves shared memory for the stencil.
// Gray halo: rows by-4..by+35, cols bx-4..bx+35 (zero pad outside image).
// Blurred tile sb[36][44]: [r][c] = blur(by-2+r, bx-4+c), valid c in 2..37.
// ---------------------------------------------------------------------------
__global__ __launch_bounds__(256) void k_blur_smax(
    const float* __restrict__ x, const float* __restrict__ tg,
    float w0, float w1, float w2)
{
    __shared__ float sgr[40][44];  // gray, rows by-4.., cols bx-4..bx+35
    __shared__ float sh[40][37];   // horiz blurred, cols bx-2..bx+33
    __shared__ float sb[36][44];   // fully blurred, rows by-2.., cols base bx-4
    __shared__ float red[8];

    const int b  = blockIdx.z;
    const int bx = blockIdx.x * 32;
    const int by = blockIdx.y * 32;
    const int tx = threadIdx.x, ty = threadIdx.y;
    const int tid = ty * 32 + tx;

    const float c0 = __ldg(tg + 0);
    const float c1 = __ldg(tg + 1);
    const float c2 = __ldg(tg + 2);
    const float* xb = x + (size_t)b * 3 * NPIX;

    const bool xedge = (blockIdx.x == 0) || (blockIdx.x == (WW / 32 - 1));
    const bool edge  = xedge || (blockIdx.y == 0) || (blockIdx.y == (HH / 32 - 1));

    // ---- load gray halo (zero outside image: SAME conv zero-pads) ----
    if (!xedge) {
        for (int idx = tid; idx < 400; idx += 256) {
            int r  = idx / 10;
            int c4 = (idx - r * 10) * 4;
            int hh = by + r - 4;
            float4 g4 = make_float4(0.f, 0.f, 0.f, 0.f);
            if (hh >= 0 && hh < HH) {
                size_t o = (size_t)hh * WW + (bx - 4) + c4;
                float4 a = *(const float4*)(xb + o);
                float4 v = *(const float4*)(xb + NPIX + o);
                float4 w = *(const float4*)(xb + 2 * NPIX + o);
                g4.x = c0 * a.x + c1 * v.x + c2 * w.x;
                g4.y = c0 * a.y + c1 * v.y + c2 * w.y;
                g4.z = c0 * a.z + c1 * v.z + c2 * w.z;
                g4.w = c0 * a.w + c1 * v.w + c2 * w.w;
            }
            *(float4*)&sgr[r][c4] = g4;
        }
    } else {
        for (int idx = tid; idx < 1600; idx += 256) {
            int r  = idx / 40;
            int c  = idx - r * 40;
            int hh = by + r - 4;
            int wc = bx - 4 + c;
            float v = 0.f;
            if (hh >= 0 && hh < HH && wc >= 0 && wc < WW) {
                size_t o = (size_t)hh * WW + wc;
                v = c0 * __ldg(xb + o) + c1 * __ldg(xb + NPIX + o)
                  + c2 * __ldg(xb + 2 * NPIX + o);
            }
            sgr[r][c] = v;
        }
    }
    __syncthreads();

    // ---- horizontal blur: 40 rows x 36 cols (global cols bx-2..bx+33) ----
    for (int idx = tid; idx < 1440; idx += 256) {
        int r = idx / 36, c = idx - r * 36;   // sh col c -> gray col index c+2
        sh[r][c] = w0 * sgr[r][c + 2]
                 + w1 * (sgr[r][c + 1] + sgr[r][c + 3])
                 + w2 * (sgr[r][c] + sgr[r][c + 4]);
    }
    __syncthreads();

    // ---- vertical blur: 36 rows x 36 cols into sb (col offset +2) ----
    for (int idx = tid; idx < 1296; idx += 256) {
        int r = idx / 36, c = idx - r * 36;
        sb[r][c + 2] = w0 * sh[r + 2][c]
                     + w1 * (sh[r + 1][c] + sh[r + 3][c])
                     + w2 * (sh[r][c] + sh[r + 4][c]);
    }
    __syncthreads();

    // ---- write blurred center 32x32 to global ----
    float* gb = g_blur + (size_t)b * NPIX;
    const int r0 = ty * 4;
    #pragma unroll
    for (int k = 0; k < 4; k++)
        gb[(size_t)(by + r0 + k) * WW + bx + tx] = sb[r0 + 2 + k][tx + 4];

    // ---- per-block max of s^2 on the in-smem blurred tile ----
    const int lj = tx + 4;
    float m = 0.0f;
    if (!edge) {
        float h00[4], h01[4], h11[4];
        hess4_fast(sb, r0, lj, h00, h01, h11);
        #pragma unroll
        for (int k = 0; k < 4; k++) {
            float mean = 0.5f * (h00[k] + h11[k]);
            float d    = 0.5f * (h00[k] - h11[k]);
            float q    = fmaf(d, d, h01[k] * h01[k]);
            m = fmaxf(m, 2.0f * fmaf(mean, mean, q));
        }
    } else {
        const int gj = bx + tx;
        #pragma unroll
        for (int k = 0; k < 4; k++) {
            int li = r0 + 2 + k, gi = by + r0 + k;
            float h00, h01, h11;
            hess_generic(sb, li, lj, gi, gj, h00, h01, h11);
            float mean = 0.5f * (h00 + h11);
            float d    = 0.5f * (h00 - h11);
            float q    = fmaf(d, d, h01 * h01);
            m = fmaxf(m, 2.0f * fmaf(mean, mean, q));
        }
    }

    #pragma unroll
    for (int o = 16; o; o >>= 1)
        m = fmaxf(m, __shfl_xor_sync(0xffffffffu, m, o));
    if (tx == 0) red[ty] = m;
    __syncthreads();
    if (tid == 0) {
        float mm = red[0];
        #pragma unroll
        for (int i = 1; i < 8; i++) mm = fmaxf(mm, red[i]);
        g_pmax[b * 1024 + blockIdx.y * 32 + blockIdx.x] = mm;
    }
}

// ---------------------------------------------------------------------------
// Kernel 2: gamma[b] = sqrt(max s^2)/2, one warp per batch; all-zero check.
// ---------------------------------------------------------------------------
__global__ __launch_bounds__(512) void k_gamma()
{
    __shared__ float gm[BB];
    const int w    = threadIdx.x >> 5;   // warp = batch
    const int lane = threadIdx.x & 31;

    const float* p = g_pmax + w * 1024;
    float m = 0.0f;
    #pragma unroll
    for (int i = 0; i < 32; i++)
        m = fmaxf(m, p[lane + i * 32]);
    #pragma unroll
    for (int o = 16; o; o >>= 1)
        m = fmaxf(m, __shfl_xor_sync(0xffffffffu, m, o));
    if (lane == 0) gm[w] = 0.5f * sqrtf(m);
    __syncthreads();

    if (threadIdx.x == 0) {
        bool allz = true;
        #pragma unroll
        for (int b = 0; b < BB; b++)
            if (gm[b] != 0.0f) allz = false;
        #pragma unroll
        for (int b = 0; b < BB; b++)
            g_gamma[b] = allz ? 1.0f : gm[b];
    }
}

// ---------------------------------------------------------------------------
// Response. First exp factor via MUFU (__expf, arg in [-2,0], never
// flush-critical). Second factor keeps accurate expf: the 1-exp(..)->0->1.0
// flush boundary must match the reference.
// ---------------------------------------------------------------------------
__device__ __forceinline__ float response(float h00, float h01, float h11,
                                          float inv_denom)
{
    float mean = 0.5f * (h00 + h11);
    float d    = 0.5f * (h00 - h11);
    float q    = fmaf(d, d, h01 * h01);
    float disc = sqrtf(q);
    float e0   = mean - disc;
    float e1   = mean + disc;

    float ae0 = fabsf(e0), ae1 = fabsf(e1);
    float num  = fminf(ae0, ae1);                      // |lam1|
    float lam2 = fmaxf((ae1 < ae0) ? e0 : e1, 1e-10f); // larger-|.| eig, clamped
    float rb   = __fdividef(num, lam2);

    float s2   = fmaf(e0, e0, e1 * e1);
    float vals = __expf(-2.0f * rb * rb)
               * (1.0f - expf(-s2 * inv_denom));
    return (vals <= 0.0f) ? 1.0f : vals;
}

// ---------------------------------------------------------------------------
// Kernel 3: final output from g_blur.
// Tile sg[36][44]: [r][c] = blur(clamp(by-2+r), clamp(bx-4+c)).
// ---------------------------------------------------------------------------
__global__ __launch_bounds__(256) void k_out(float* __restrict__ out)
{
    __shared__ float sg[36][44];

    const int b  = blockIdx.z;
    const int bx = blockIdx.x * 32;
    const int by = blockIdx.y * 32;
    const int tx = threadIdx.x, ty = threadIdx.y;
    const int tid = ty * 32 + tx;
    const float* gb = g_blur + (size_t)b * NPIX;

    const bool xedge = (blockIdx.x == 0) || (blockIdx.x == (WW / 32 - 1));
    const bool edge  = xedge || (blockIdx.y == 0) || (blockIdx.y == (HH / 32 - 1));

    if (!xedge) {
        for (int idx = tid; idx < 360; idx += 256) {
            int r  = idx / 10;
            int c4 = (idx - r * 10) * 4;
            int hh = min(HH - 1, max(0, by + r - 2));
            *(float4*)&sg[r][c4] =
                *(const float4*)(gb + (size_t)hh * WW + (bx - 4) + c4);
        }
    } else {
        for (int idx = tid; idx < 1440; idx += 256) {
            int r  = idx / 40;
            int c  = idx - r * 40;
            int hh = min(HH - 1, max(0, by + r - 2));
            int wc = min(WW - 1, max(0, bx - 4 + c));
            sg[r][c] = __ldg(gb + (size_t)hh * WW + wc);
        }
    }
    __syncthreads();

    const float gamma = g_gamma[b];
    const float inv_denom = 1.0f / (2.0f * gamma * gamma);
    float* ob = out + (size_t)b * NPIX;

    const int lj = tx + 4;
    const int r0 = ty * 4;

    if (!edge) {
        float h00[4], h01[4], h11[4];
        hess4_fast(sg, r0, lj, h00, h01, h11);
        #pragma unroll
        for (int k = 0; k < 4; k++) {
            ob[(size_t)(by + r0 + k) * WW + bx + tx] =
                response(h00[k], h01[k], h11[k], inv_denom);
        }
    } else {
        const int gj = bx + tx;
        #pragma unroll
        for (int k = 0; k < 4; k++) {
            int li = r0 + 2 + k, gi = by + r0 + k;
            float h00, h01, h11;
            hess_generic(sg, li, lj, gi, gj, h00, h01, h11);
            ob[(size_t)gi * WW + gj] = response(h00, h01, h11, inv_denom);
        }
    }
}

// ---------------------------------------------------------------------------
extern "C" void kernel_launch(void* const* d_in, const int* in_sizes, int n_in,
                              void* d_out, int out_size)
{
    const float* x  = (const float*)d_in[0];
    const float* tg = (const float*)d_in[1];
    if (n_in >= 2 && in_sizes[0] == 3) {  // robust to input ordering
        const float* t = x; x = tg; tg = t;
    }

    // Separable normalized Gaussian weights, L=5, sig=10.
    double e1d = exp(-0.005), e2d = exp(-0.02);
    double S = 1.0 + 2.0 * e1d + 2.0 * e2d;
    float w0 = (float)(1.0 / S);
    float w1 = (float)(e1d / S);
    float w2 = (float)(e2d / S);

    dim3 blk(32, 8);
    dim3 grd(WW / 32, HH / 32, BB);

    k_blur_smax<<<grd, blk>>>(x, tg, w0, w1, w2);
    k_gamma<<<1, 512>>>();
    k_out<<<grd, blk>>>((float*)d_out);
}